// round 16
// baseline (speedup 1.0000x reference)
#include <cuda_runtime.h>
#include <math.h>
#include <stdint.h>

// Problem dims
#define XD 512
#define YD 512
#define ZD 32
#define PLANE (XD*YD)          // 262144
#define NTOT (PLANE*ZD)        // 8388608
#define WXW 492
#define WYW 492
#define WZW 28
#define AD 21
#define BD 21
#define CD 5
#define NCCN (AD*BD*CD)        // 2205
#define EPSV 1e-8

#define POOLSZ 593             // line stride (float2); max used index 574
#define SMEMB  (32*POOLSZ*sizeof(float2))   // 151808 B (fwd_zy / inv_yz)
#define SMEMXC (16*POOLSZ*sizeof(float2))   // 75904 B  (k_xc, 2 blocks/SM)

// ---------------- scratch (static device globals; no runtime alloc) --------
__device__ float2 g_buf[NTOT];             // 67 MB complex work buffer (fp32)
__device__ float2 g_side[2*PLANE];         // self-mirror planes z=0,16
__device__ float2 g_P1[PLANE*CD];          // z-window sums of (img, img^2)
__device__ float2 g_P2[XD*BD*CD];          // +y-window sums
__device__ double g_denom[NCCN];
__device__ double g_part[1024*3];          // [1024..1535]=tpl sum, [2048..2559]=tpl sumsq
__device__ float2 g_tw512f[512];           // e^{-2*pi*i*j/512}
__device__ float2 g_tw32[16];

// ---------------- complex helpers -------------------------------------------
__device__ __forceinline__ float2 cadd(float2 a, float2 b){ return make_float2(a.x+b.x, a.y+b.y); }
__device__ __forceinline__ float2 csub(float2 a, float2 b){ return make_float2(a.x-b.x, a.y-b.y); }

template<bool INV>
__device__ __forceinline__ float2 twmul(float2 v, int idx) {
    float2 w = g_tw512f[idx];
    float wy = INV ? -w.y : w.y;
    return make_float2(v.x*w.x - v.y*wy, v.x*wy + v.y*w.x);
}

// 8-point DFT in registers, natural-order bins.
template<bool INV>
__device__ __forceinline__ void dft8(float2* r) {
    const float C = 0.70710678118654752f;
    float2 a0 = cadd(r[0], r[4]), b0 = csub(r[0], r[4]);
    float2 a1 = cadd(r[1], r[5]), b1 = csub(r[1], r[5]);
    float2 a2 = cadd(r[2], r[6]), b2 = csub(r[2], r[6]);
    float2 a3 = cadd(r[3], r[7]), b3 = csub(r[3], r[7]);
    b1 = INV ? make_float2(C*(b1.x-b1.y),  C*(b1.x+b1.y))
             : make_float2(C*(b1.x+b1.y),  C*(b1.y-b1.x));
    b2 = INV ? make_float2(-b2.y, b2.x) : make_float2(b2.y, -b2.x);
    b3 = INV ? make_float2(-C*(b3.x+b3.y), C*(b3.x-b3.y))
             : make_float2(C*(b3.y-b3.x), -C*(b3.x+b3.y));
    float2 p0 = cadd(a0,a2), q0 = csub(a0,a2);
    float2 p1 = cadd(a1,a3), q1 = csub(a1,a3);
    q1 = INV ? make_float2(-q1.y, q1.x) : make_float2(q1.y, -q1.x);
    r[0]=cadd(p0,p1); r[4]=csub(p0,p1); r[2]=cadd(q0,q1); r[6]=csub(q0,q1);
    p0 = cadd(b0,b2); q0 = csub(b0,b2);
    p1 = cadd(b1,b3); q1 = csub(b1,b3);
    q1 = INV ? make_float2(-q1.y, q1.x) : make_float2(q1.y, -q1.x);
    r[1]=cadd(p0,p1); r[5]=csub(p0,p1); r[3]=cadd(q0,q1); r[7]=csub(q0,q1);
}

// 512-pt FFT. STORE=true: on exit pool[g+(g>>3)] holds X[g] (natural order).
// STORE=false: returns with r[m] = X[64*m + q], q = 8*(u&7) + (u>>3).
template<bool INV, bool STORE>
__device__ __forceinline__ void fft512_core(float2 r[8], float2* pool, int u) {
    dft8<INV>(r);
#pragma unroll
    for (int k = 1; k < 8; k++) r[k] = twmul<INV>(r[k], (u*k) & 511);
    __syncthreads();
#pragma unroll
    for (int k = 0; k < 8; k++) pool[k*65 + u] = r[k];
    __syncthreads();
    int k2 = u >> 3, ap = u & 7;
#pragma unroll
    for (int b = 0; b < 8; b++) r[b] = pool[k2*65 + ap + 8*b];
    dft8<INV>(r);
#pragma unroll
    for (int k = 1; k < 8; k++) r[k] = twmul<INV>(r[k], 8*ap*k);
    __syncthreads();
#pragma unroll
    for (int k = 0; k < 8; k++) pool[(k2*8 + k)*9 + ap] = r[k];
    __syncthreads();
#pragma unroll
    for (int a = 0; a < 8; a++) r[a] = pool[u*9 + a];
    dft8<INV>(r);
    if (STORE) {
        __syncthreads();
        int q = 8*ap + k2;   // f = 64*m + q
#pragma unroll
        for (int m = 0; m < 8; m++) { int f = 64*m + q; pool[f + (f>>3)] = r[m]; }
        __syncthreads();
    }
}

// ---------------- init: twiddle tables (idempotent) --------------------------
__global__ void k_init() {
    int t = threadIdx.x;
    if (t < 512) { double s, c; sincospi(-(double)t/256.0, &s, &c); g_tw512f[t] = make_float2((float)c, (float)s); }
    if (t < 16)  { double s, c; sincospi(-(double)t/16.0,  &s, &c); g_tw32[t]  = make_float2((float)c, (float)s); }
}

// ---------------- 32-pt warp-shuffle FFT (one point per lane) ---------------
template<bool INV>
__device__ __forceinline__ float2 fft32_warp(float2 v, int lane) {
#pragma unroll
    for (int h = 16; h >= 1; h >>= 1) {
        float ox = __shfl_xor_sync(0xffffffffu, v.x, h);
        float oy = __shfl_xor_sync(0xffffffffu, v.y, h);
        int t = lane & (h - 1);
        float2 w = g_tw32[t * (16 / h)];
        float wy = INV ? -w.y : w.y;
        if ((lane & h) == 0) { v.x += ox; v.y += oy; }
        else {
            float dx = ox - v.x, dy = oy - v.y;
            v.x = dx*w.x - dy*wy;
            v.y = dx*wy + dy*w.x;
        }
    }
    int rl = __brev(lane) >> 27;
    float nx = __shfl_sync(0xffffffffu, v.x, rl);
    float ny = __shfl_sync(0xffffffffu, v.y, rl);
    return make_float2(nx, ny);
}

// ---- fused: forward z-FFT + y-FFT + tpl sums + z-window sums (block per x) --
// y-FFT final round stores straight from registers to g_buf.
__global__ void __launch_bounds__(1024) k_fwd_zy(const float* __restrict__ fr,
                                                 const float* __restrict__ tpl) {
    extern __shared__ float2 tile[];   // 32 lines (z) x POOLSZ
    __shared__ double w1[32], w2[32];
    int x = blockIdx.x;
    int t = threadIdx.x;
    int w = t >> 5, lane = t & 31;
    float a1 = 0.f, a2 = 0.f;
#pragma unroll
    for (int i = 0; i < 16; i++) {
        int y = w + 32*i;
        size_t base = ((size_t)x*512 + y)*ZD + lane;
        float fv = fr[base];
        float tv = tpl[base];
        a1 += tv; a2 += tv*tv;
        float sA = fv, sB = fv*fv;
#pragma unroll
        for (int o = 1; o < 32; o <<= 1) {
            float tA = __shfl_up_sync(0xffffffffu, sA, o);
            float tB = __shfl_up_sync(0xffffffffu, sB, o);
            if (lane >= o) { sA += tA; sB += tB; }
        }
        float hA = __shfl_sync(0xffffffffu, sA, 27 + lane);  // used by lane<5
        float hB = __shfl_sync(0xffffffffu, sB, 27 + lane);
        float lA = __shfl_sync(0xffffffffu, sA, lane - 1);
        float lB = __shfl_sync(0xffffffffu, sB, lane - 1);
        if (lane < 5) {
            float loA = (lane == 0) ? 0.f : lA;
            float loB = (lane == 0) ? 0.f : lB;
            g_P1[((size_t)x*512 + y)*5 + lane] = make_float2(hA - loA, hB - loB);
        }
        float2 v = make_float2(fv, tv);
        v = fft32_warp<false>(v, lane);
        tile[lane*POOLSZ + y] = v;
    }
    {
        double d1 = (double)a1, d2 = (double)a2;
#pragma unroll
        for (int o = 16; o > 0; o >>= 1) {
            d1 += __shfl_down_sync(0xffffffffu, d1, o);
            d2 += __shfl_down_sync(0xffffffffu, d2, o);
        }
        if (lane == 0) { w1[w] = d1; w2[w] = d2; }
    }
    __syncthreads();
    if (w == 0) {
        double d1 = w1[lane], d2 = w2[lane];
#pragma unroll
        for (int o = 16; o > 0; o >>= 1) {
            d1 += __shfl_down_sync(0xffffffffu, d1, o);
            d2 += __shfl_down_sync(0xffffffffu, d2, o);
        }
        if (lane == 0) { g_part[1024 + x] = d1; g_part[2048 + x] = d2; }
    }
    int l0 = t >> 6, u = t & 63;
    int q = ((u & 7) << 3) | (u >> 3);
#pragma unroll
    for (int c = 0; c < 2; c++) {
        int l = c*16 + l0;            // line = z
        float2* pool = tile + l*POOLSZ;
        float2 r[8];
#pragma unroll
        for (int b = 0; b < 8; b++) r[b] = pool[u + 64*b];
        fft512_core<false, false>(r, pool, u);
        float2* dst = g_buf + (size_t)l*PLANE + (size_t)x*512;
#pragma unroll
        for (int m = 0; m < 8; m++) dst[64*m + q] = r[m];
    }
}

// ------- unified forward x-FFT + cross + inverse x-FFT ----------------------
// 17 planes x 64 y-groups; 512 threads; 16-line tile (8 primary + 8 mirror).
__global__ void __launch_bounds__(512) k_xc() {
    extern __shared__ float2 pool16[];   // 16 x POOLSZ
    int t = threadIdx.x;
    int p = blockIdx.x >> 6;             // 0..16
    int y0 = (blockIdx.x & 63) << 3;
    int zm = (32 - p) & 31;
#pragma unroll
    for (int k = 0; k < 16; k++) {
        int e = t + k*512;
        int x = e >> 4, L = e & 15;
        int l = L & 7;
        int plane = (L < 8) ? p : zm;
        int y = (L < 8) ? (y0 + l) : ((512 - (y0 + l)) & 511);
        pool16[L*POOLSZ + x] = g_buf[(size_t)plane*PLANE + (size_t)x*512 + y];
    }
    __syncthreads();
    int l0 = t >> 6, u = t & 63;
#pragma unroll
    for (int c = 0; c < 2; c++) {
        int Q = c*8 + l0;
        float2* pool = pool16 + Q*POOLSZ;
        float2 r[8];
#pragma unroll
        for (int b = 0; b < 8; b++) r[b] = pool[u + 64*b];
        fft512_core<false, true>(r, pool, u);
    }
    float2* pool = pool16 + l0*POOLSZ;
    float2* mpool = pool16 + (l0 + 8)*POOLSZ;
    float2 r[8];
#pragma unroll
    for (int b = 0; b < 8; b++) {
        int x = u + 64*b;
        int xm = (512 - x) & 511;
        float2 a  = pool[x + (x>>3)];
        float2 bb = mpool[xm + (xm>>3)];
        float sx = a.x + bb.x, sy = a.y - bb.y;
        float tx = a.x - bb.x, ty = -a.y - bb.y;
        float ur = sx*tx - sy*ty;
        float ui = sx*ty + sy*tx;
        r[b] = make_float2(-0.25f*ui, 0.25f*ur);
    }
    if (p == 0 && y0 == 0 && l0 == 0 && u == 0)
        r[0] = make_float2(0.f, 0.f);   // exact DC of zero-mean cross
    __syncthreads();
    fft512_core<true, true>(r, pool, u);
    float2* dst;
    if (p == 0)       dst = g_side;
    else if (p == 16) dst = g_side + PLANE;
    else              dst = g_buf + (size_t)p*PLANE;
#pragma unroll
    for (int k = 0; k < 8; k++) {
        int e = t + k*512;
        int x = e >> 3, yy = e & 7;
        dst[(size_t)x*512 + (y0 + yy)] = pool16[yy*POOLSZ + x + (x>>3)];
    }
}

// ------- fused inverse y + inverse z + roll/abs/store, 2-for-1 in x ---------
// Dual-write loads: planes 1..15 loaded once, feeding line z (packed a+ib)
// and line 32-z at mirrored y (conj(a)+i*conj(b)) simultaneously.
__global__ void __launch_bounds__(1024) k_inv_yz(float* __restrict__ out) {
    extern __shared__ float2 tile[];   // 32 lines (z) x POOLSZ
    int x1 = blockIdx.x, x2 = x1 + 256;
    int t = threadIdx.x;
    // side planes z=0,16 (self-mirror)
    {
        int y = t & 511;
        const float2* src = (t < 512) ? g_side : (g_side + PLANE);
        int z = (t < 512) ? 0 : 16;
        float2 a = src[(size_t)x1*512 + y];
        float2 b = src[(size_t)x2*512 + y];
        tile[z*POOLSZ + y] = make_float2(a.x - b.y, a.y + b.x);
    }
    // planes 1..15: load once, write line z and conj-mirror line 32-z
#pragma unroll
    for (int k = 0; k < 8; k++) {
        int e = t + k*1024;
        if (e < 7680) {
            int z = (e >> 9) + 1;       // 1..15
            int y = e & 511;
            const float2* src = g_buf + (size_t)z*PLANE;
            float2 a = src[(size_t)x1*512 + y];
            float2 b = src[(size_t)x2*512 + y];
            tile[z*POOLSZ + y] = make_float2(a.x - b.y, a.y + b.x);
            int ym = (512 - y) & 511;
            tile[(32 - z)*POOLSZ + ym] = make_float2(a.x + b.y, b.x - a.y);
        }
    }
    __syncthreads();
    int l0 = t >> 6, u = t & 63;
#pragma unroll
    for (int c = 0; c < 2; c++) {
        int l = c*16 + l0;
        float2* pool = tile + l*POOLSZ;
        float2 r[8];
#pragma unroll
        for (int b = 0; b < 8; b++) r[b] = pool[u + 64*b];
        fft512_core<true, true>(r, pool, u);
    }
    int w = t >> 5, lane = t & 31;
    int ox1 = (x1 + 256) & 511;   // = x2
    int ox2 = (x2 + 256) & 511;   // = x1
    int oz = (lane + 16) & 31;
    const float inv = 1.0f / (float)NTOT;
#pragma unroll
    for (int i = 0; i < 16; i++) {
        int y = w + 32*i;
        float2 v = tile[lane*POOLSZ + y + (y>>3)];
        v = fft32_warp<true>(v, lane);
        int oy = (y + 256) & 511;
        out[3 + (((ox1 << 9) | oy) << 5) + oz] = fabsf(v.x) * inv;
        out[3 + (((ox2 << 9) | oy) << 5) + oz] = fabsf(v.y) * inv;
    }
}

// ---------------- y-window pass: F - head - tail (block per x) ---------------
__global__ void k_yred() {
    __shared__ float2 sh[512*5];
    __shared__ float2 part[32][5];
    int x = blockIdx.x, t = threadIdx.x;   // 256 threads
    for (int i = t; i < 512*5; i += 256) sh[i] = g_P1[(size_t)x*(512*5) + i];
    __syncthreads();
    if (t < 160) {
        int c = t % 5, chunk = t / 5;
        float A = 0.f, B = 0.f;
#pragma unroll
        for (int j = 0; j < 16; j++) {
            float2 v = sh[(chunk*16 + j)*5 + c];
            A += v.x; B += v.y;
        }
        part[chunk][c] = make_float2(A, B);
    }
    __syncthreads();
    if (t < 5) {
        int c = t;
        float FA = 0.f, FB = 0.f;
#pragma unroll
        for (int k = 0; k < 32; k++) { FA += part[k][c].x; FB += part[k][c].y; }
        float headA[21], headB[21], tailA[21], tailB[21];
        headA[0] = 0.f; headB[0] = 0.f;
        for (int b = 1; b <= 20; b++) {
            float2 v = sh[(b-1)*5 + c];
            headA[b] = headA[b-1] + v.x; headB[b] = headB[b-1] + v.y;
        }
        tailA[20] = 0.f; tailB[20] = 0.f;
        for (int b = 19; b >= 0; b--) {
            float2 v = sh[(b + 492)*5 + c];
            tailA[b] = tailA[b+1] + v.x; tailB[b] = tailB[b+1] + v.y;
        }
        for (int b = 0; b < 21; b++)
            g_P2[(x*BD + b)*5 + c] = make_float2(FA - headA[b] - tailA[b],
                                                 FB - headB[b] - tailB[b]);
    }
}

// ---- x-window + denominator (tplvar reduced inline per block) ---------------
__global__ void k_xred() {
    __shared__ double sp[256];
    __shared__ double s_sum1, s_tv;
    int t = threadIdx.x;
    sp[t] = g_part[1024 + t] + g_part[1024 + 256 + t];
    __syncthreads();
    for (int o = 128; o > 0; o >>= 1) { if (t < o) sp[t] += sp[t+o]; __syncthreads(); }
    if (t == 0) s_sum1 = sp[0];
    __syncthreads();
    sp[t] = g_part[2048 + t] + g_part[2048 + 256 + t];
    __syncthreads();
    for (int o = 128; o > 0; o >>= 1) { if (t < o) sp[t] += sp[t+o]; __syncthreads(); }
    if (t == 0) {
        double mt = s_sum1 / (double)NTOT;
        s_tv = sp[0] - (double)NTOT*mt*mt + EPSV;
    }
    __syncthreads();
    double tplvar = s_tv;
    int gw = blockIdx.x*8 + (t >> 5);
    int lane = t & 31;
    if (gw >= NCCN) return;
    int a = gw / (BD*CD), rr = gw % (BD*CD), b = rr / CD, c = rr % CD;
    double A = 0, B = 0;
    for (int j = lane; j < 492; j += 32) {
        float2 v = g_P2[((size_t)(a + j)*BD + b)*CD + c];
        A += (double)v.x; B += (double)v.y;
    }
#pragma unroll
    for (int o = 16; o > 0; o >>= 1) {
        A += __shfl_down_sync(0xffffffffu, A, o);
        B += __shfl_down_sync(0xffffffffu, B, o);
    }
    if (lane == 0) {
        const double wn = (double)WXW * (double)WYW * (double)WZW;
        double m1 = A / wn, m2 = B / wn;
        double var = m2 - m1*m1/(double)NTOT + EPSV;
        if (var < 0) var = 0;
        g_denom[gw] = sqrt(tplvar * var);
    }
}

// ---------------- ncc + argmax + subpixel (single block) ---------------------
__global__ void k_ncc_argmax(float* __restrict__ out) {
    __shared__ float ncc_s[NCCN];
    __shared__ float sv[256];
    __shared__ int   si[256];
    int t = threadIdx.x;
    for (int q = t; q < NCCN; q += 256) {
        int a = q / (BD*CD), rr = q % (BD*CD), b = rr / CD, c = rr % CD;
        int ridx = ((((246 + a) << 9) | (246 + b)) << 5) | (14 + c);
        float val = out[3 + ridx] / (float)g_denom[q];
        if (val != val) val = 0.0f;
        out[3 + NTOT + q] = val;
        ncc_s[q] = val;
    }
    __syncthreads();
    float bv = -1e30f; int bi = 0x7fffffff;
    for (int q = t; q < NCCN; q += 256) {
        float v = ncc_s[q];
        if (v > bv) { bv = v; bi = q; }
    }
    sv[t] = bv; si[t] = bi; __syncthreads();
    for (int o = 128; o > 0; o >>= 1) {
        if (t < o) {
            if (sv[t+o] > sv[t] || (sv[t+o] == sv[t] && si[t+o] < si[t])) {
                sv[t] = sv[t+o]; si[t] = si[t+o];
            }
        }
        __syncthreads();
    }
    if (t == 0) {
        int idx = si[0];
        int sx = idx / (BD*CD), sy = (idx % (BD*CD)) / CD, sz = idx % CD;
        auto L = [&](int dx, int dy, int dz) {
            int xi = sx + dx; if (xi < 0) xi = 0; if (xi > AD-1) xi = AD-1;
            int yi = sy + dy; if (yi < 0) yi = 0; if (yi > BD-1) yi = BD-1;
            int zi = sz + dz; if (zi < 0) zi = 0; if (zi > CD-1) zi = CD-1;
            return logf(ncc_s[(xi*BD + yi)*CD + zi]);
        };
        float six = 6.0f * L(0,0,0);
        float shx = -(float)(sx - 10) - (L(-1,0,0) - L(1,0,0)) / (2.0f*L(-1,0,0) - six + 2.0f*L(1,0,0));
        float shy = -(float)(sy - 10) - (L(0,-1,0) - L(0,1,0)) / (2.0f*L(0,-1,0) - six + 2.0f*L(0,1,0));
        float shz = -(float)(sz - 2)  - (L(0,0,-1) - L(0,0,1)) / (2.0f*L(0,0,-1) - six + 2.0f*L(0,0,1));
        out[0] = shx; out[1] = shy; out[2] = shz;
    }
}

// ---------------- launch ------------------------------------------------------
extern "C" void kernel_launch(void* const* d_in, const int* in_sizes, int n_in,
                              void* d_out, int out_size) {
    const float* fr  = (const float*)d_in[0];   // (1,512,512,32,1)
    const float* tpl = (const float*)d_in[1];   // (512,512,32,1)
    float* out = (float*)d_out;                 // [shx,shy,shz, rolled_cc(8.4M), ncc(2205)]

    cudaFuncSetAttribute(k_fwd_zy, cudaFuncAttributeMaxDynamicSharedMemorySize, (int)SMEMB);
    cudaFuncSetAttribute(k_inv_yz, cudaFuncAttributeMaxDynamicSharedMemorySize, (int)SMEMB);
    cudaFuncSetAttribute(k_xc,     cudaFuncAttributeMaxDynamicSharedMemorySize, (int)SMEMXC);

    // three idempotent init launches so the ncu capture slot (4th launch)
    // finally lands on k_fwd_zy — the largest, so-far-unprofiled kernel.
    k_init  <<<1, 512>>>();
    k_init  <<<1, 512>>>();
    k_init  <<<1, 512>>>();

    // forward z+y FFT + tpl sums + z-window sums (direct-register y stores)
    k_fwd_zy<<<XD, 1024, SMEMB>>>(fr, tpl);

    // unified forward-x + cross + inverse-x (17 planes, 2 blocks/SM)
    k_xc<<<17*64, 512, SMEMXC>>>();

    // fused inverse y + inverse z + roll/abs (dual-write loads, conj mirror)
    k_inv_yz<<<256, 1024, SMEMB>>>(out);

    // denominator chain (tplvar folded into k_xred)
    k_yred<<<XD, 256>>>();
    k_xred<<<(NCCN + 7)/8, 256>>>();

    // ncc + subpixel shifts
    k_ncc_argmax<<<1, 256>>>(out);
}

// round 17
// speedup vs baseline: 1.0559x; 1.0559x over previous
#include <cuda_runtime.h>
#include <math.h>
#include <stdint.h>

// Problem dims
#define XD 512
#define YD 512
#define ZD 32
#define PLANE (XD*YD)          // 262144
#define NTOT (PLANE*ZD)        // 8388608
#define WXW 492
#define WYW 492
#define WZW 28
#define AD 21
#define BD 21
#define CD 5
#define NCCN (AD*BD*CD)        // 2205
#define EPSV 1e-8

#define POOLSZ 593             // line stride (float2); max used index 574
#define SMEMB  (32*POOLSZ*sizeof(float2))   // 151808 B (fwd_zy / inv_yz)
#define SMEMXC (16*POOLSZ*sizeof(float2))   // 75904 B  (k_xc, 2 blocks/SM)

// ---------------- scratch (static device globals; no runtime alloc) --------
__device__ float2 g_buf[NTOT];             // 67 MB complex work buffer (fp32)
__device__ float2 g_side[2*PLANE];         // self-mirror planes z=0,16
__device__ float2 g_P1[PLANE*CD];          // z-window sums of (img, img^2)
__device__ float2 g_P2[XD*BD*CD];          // +y-window sums
__device__ double g_denom[NCCN];
__device__ double g_part[1024*3];          // [1024..1535]=tpl sum, [2048..2559]=tpl sumsq
__device__ float2 g_tw512f[512];           // e^{-2*pi*i*j/512}
__device__ float2 g_tw32[16];

// ---------------- complex helpers -------------------------------------------
__device__ __forceinline__ float2 cadd(float2 a, float2 b){ return make_float2(a.x+b.x, a.y+b.y); }
__device__ __forceinline__ float2 csub(float2 a, float2 b){ return make_float2(a.x-b.x, a.y-b.y); }

template<bool INV>
__device__ __forceinline__ float2 twmul(float2 v, int idx) {
    float2 w = g_tw512f[idx];
    float wy = INV ? -w.y : w.y;
    return make_float2(v.x*w.x - v.y*wy, v.x*wy + v.y*w.x);
}

// 8-point DFT in registers, natural-order bins.
template<bool INV>
__device__ __forceinline__ void dft8(float2* r) {
    const float C = 0.70710678118654752f;
    float2 a0 = cadd(r[0], r[4]), b0 = csub(r[0], r[4]);
    float2 a1 = cadd(r[1], r[5]), b1 = csub(r[1], r[5]);
    float2 a2 = cadd(r[2], r[6]), b2 = csub(r[2], r[6]);
    float2 a3 = cadd(r[3], r[7]), b3 = csub(r[3], r[7]);
    b1 = INV ? make_float2(C*(b1.x-b1.y),  C*(b1.x+b1.y))
             : make_float2(C*(b1.x+b1.y),  C*(b1.y-b1.x));
    b2 = INV ? make_float2(-b2.y, b2.x) : make_float2(b2.y, -b2.x);
    b3 = INV ? make_float2(-C*(b3.x+b3.y), C*(b3.x-b3.y))
             : make_float2(C*(b3.y-b3.x), -C*(b3.x+b3.y));
    float2 p0 = cadd(a0,a2), q0 = csub(a0,a2);
    float2 p1 = cadd(a1,a3), q1 = csub(a1,a3);
    q1 = INV ? make_float2(-q1.y, q1.x) : make_float2(q1.y, -q1.x);
    r[0]=cadd(p0,p1); r[4]=csub(p0,p1); r[2]=cadd(q0,q1); r[6]=csub(q0,q1);
    p0 = cadd(b0,b2); q0 = csub(b0,b2);
    p1 = cadd(b1,b3); q1 = csub(b1,b3);
    q1 = INV ? make_float2(-q1.y, q1.x) : make_float2(q1.y, -q1.x);
    r[1]=cadd(p0,p1); r[5]=csub(p0,p1); r[3]=cadd(q0,q1); r[7]=csub(q0,q1);
}

// 512-pt FFT. STORE=true: on exit pool[g+(g>>3)] holds X[g] (natural order).
// STORE=false: returns with r[m] = X[64*m + q], q = 8*(u&7) + (u>>3).
template<bool INV, bool STORE>
__device__ __forceinline__ void fft512_core(float2 r[8], float2* pool, int u) {
    dft8<INV>(r);
#pragma unroll
    for (int k = 1; k < 8; k++) r[k] = twmul<INV>(r[k], (u*k) & 511);
    __syncthreads();
#pragma unroll
    for (int k = 0; k < 8; k++) pool[k*65 + u] = r[k];
    __syncthreads();
    int k2 = u >> 3, ap = u & 7;
#pragma unroll
    for (int b = 0; b < 8; b++) r[b] = pool[k2*65 + ap + 8*b];
    dft8<INV>(r);
#pragma unroll
    for (int k = 1; k < 8; k++) r[k] = twmul<INV>(r[k], 8*ap*k);
    __syncthreads();
#pragma unroll
    for (int k = 0; k < 8; k++) pool[(k2*8 + k)*9 + ap] = r[k];
    __syncthreads();
#pragma unroll
    for (int a = 0; a < 8; a++) r[a] = pool[u*9 + a];
    dft8<INV>(r);
    if (STORE) {
        __syncthreads();
        int q = 8*ap + k2;   // f = 64*m + q
#pragma unroll
        for (int m = 0; m < 8; m++) { int f = 64*m + q; pool[f + (f>>3)] = r[m]; }
        __syncthreads();
    }
}

// ---------------- init: twiddle tables (idempotent) --------------------------
__global__ void k_init() {
    int t = threadIdx.x;
    if (t < 512) { double s, c; sincospi(-(double)t/256.0, &s, &c); g_tw512f[t] = make_float2((float)c, (float)s); }
    if (t < 16)  { double s, c; sincospi(-(double)t/16.0,  &s, &c); g_tw32[t]  = make_float2((float)c, (float)s); }
}

// ---------------- 32-pt warp-shuffle FFT (one point per lane) ---------------
template<bool INV>
__device__ __forceinline__ float2 fft32_warp(float2 v, int lane) {
#pragma unroll
    for (int h = 16; h >= 1; h >>= 1) {
        float ox = __shfl_xor_sync(0xffffffffu, v.x, h);
        float oy = __shfl_xor_sync(0xffffffffu, v.y, h);
        int t = lane & (h - 1);
        float2 w = g_tw32[t * (16 / h)];
        float wy = INV ? -w.y : w.y;
        if ((lane & h) == 0) { v.x += ox; v.y += oy; }
        else {
            float dx = ox - v.x, dy = oy - v.y;
            v.x = dx*w.x - dy*wy;
            v.y = dx*wy + dy*w.x;
        }
    }
    int rl = __brev(lane) >> 27;
    float nx = __shfl_sync(0xffffffffu, v.x, rl);
    float ny = __shfl_sync(0xffffffffu, v.y, rl);
    return make_float2(nx, ny);
}

// ---- fused: forward z-FFT + y-FFT + tpl sums + z-window sums (block per x) --
// Stage 1 of the y-FFT is done IN REGISTERS by the z-phase: thread (w,lane)
// iterates y = u + 64b (u = w, w+32), so after fft32 it holds exactly the
// stage-1 radix-8 inputs of line z=lane; dft8 + twiddle in regs, write the
// 65-stride layout directly. Stages 2-3 then run with the 64-thr/line map,
// final round stores straight from registers to g_buf.
__global__ void __launch_bounds__(1024) k_fwd_zy(const float* __restrict__ fr,
                                                 const float* __restrict__ tpl) {
    extern __shared__ float2 tile[];   // 32 lines (z) x POOLSZ
    __shared__ double w1s[32], w2s[32];
    int x = blockIdx.x;
    int t = threadIdx.x;
    int w = t >> 5, lane = t & 31;
    float a1 = 0.f, a2 = 0.f;
#pragma unroll
    for (int half = 0; half < 2; half++) {
        int u = w + 32*half;
        float2 X[8];
#pragma unroll
        for (int b = 0; b < 8; b++) {
            int y = u + 64*b;
            size_t base = ((size_t)x*512 + y)*ZD + lane;
            float fv = fr[base];
            float tv = tpl[base];
            a1 += tv; a2 += tv*tv;
            float sA = fv, sB = fv*fv;
#pragma unroll
            for (int o = 1; o < 32; o <<= 1) {
                float tA = __shfl_up_sync(0xffffffffu, sA, o);
                float tB = __shfl_up_sync(0xffffffffu, sB, o);
                if (lane >= o) { sA += tA; sB += tB; }
            }
            float hA = __shfl_sync(0xffffffffu, sA, 27 + lane);  // used by lane<5
            float hB = __shfl_sync(0xffffffffu, sB, 27 + lane);
            float lA = __shfl_sync(0xffffffffu, sA, lane - 1);
            float lB = __shfl_sync(0xffffffffu, sB, lane - 1);
            if (lane < 5) {
                float loA = (lane == 0) ? 0.f : lA;
                float loB = (lane == 0) ? 0.f : lB;
                g_P1[((size_t)x*512 + y)*5 + lane] = make_float2(hA - loA, hB - loB);
            }
            X[b] = fft32_warp<false>(make_float2(fv, tv), lane);
        }
        // stage-1 dft8 + twiddle in registers, write 65-layout of line z=lane
        dft8<false>(X);
#pragma unroll
        for (int k = 1; k < 8; k++) X[k] = twmul<false>(X[k], (u*k) & 511);
        float2* pool = tile + lane*POOLSZ;
#pragma unroll
        for (int k = 0; k < 8; k++) pool[k*65 + u] = X[k];
    }
    // tpl block reduction (fp64 shuffles)
    {
        double d1 = (double)a1, d2 = (double)a2;
#pragma unroll
        for (int o = 16; o > 0; o >>= 1) {
            d1 += __shfl_down_sync(0xffffffffu, d1, o);
            d2 += __shfl_down_sync(0xffffffffu, d2, o);
        }
        if (lane == 0) { w1s[w] = d1; w2s[w] = d2; }
    }
    __syncthreads();   // covers stage-1 writes + w1s/w2s
    if (w == 0) {
        double d1 = w1s[lane], d2 = w2s[lane];
#pragma unroll
        for (int o = 16; o > 0; o >>= 1) {
            d1 += __shfl_down_sync(0xffffffffu, d1, o);
            d2 += __shfl_down_sync(0xffffffffu, d2, o);
        }
        if (lane == 0) { g_part[1024 + x] = d1; g_part[2048 + x] = d2; }
    }
    // stages 2-3: 16 lines per round, 64 thr/line, direct global stores
    int l0 = t >> 6, u = t & 63;
    int k2 = u >> 3, ap = u & 7;
    int q = 8*ap + k2;
#pragma unroll
    for (int c = 0; c < 2; c++) {
        int l = c*16 + l0;            // line = z
        float2* pool = tile + l*POOLSZ;
        float2 r[8];
#pragma unroll
        for (int b = 0; b < 8; b++) r[b] = pool[k2*65 + ap + 8*b];
        dft8<false>(r);
#pragma unroll
        for (int k = 1; k < 8; k++) r[k] = twmul<false>(r[k], 8*ap*k);
        __syncthreads();
#pragma unroll
        for (int k = 0; k < 8; k++) pool[(k2*8 + k)*9 + ap] = r[k];
        __syncthreads();
#pragma unroll
        for (int a = 0; a < 8; a++) r[a] = pool[u*9 + a];
        dft8<false>(r);
        float2* dst = g_buf + (size_t)l*PLANE + (size_t)x*512;
#pragma unroll
        for (int m = 0; m < 8; m++) dst[64*m + q] = r[m];
    }
}

// ------- unified forward x-FFT + cross + inverse x-FFT ----------------------
// 17 planes x 64 y-groups; 512 threads; 16-line tile (8 primary + 8 mirror).
__global__ void __launch_bounds__(512) k_xc() {
    extern __shared__ float2 pool16[];   // 16 x POOLSZ
    int t = threadIdx.x;
    int p = blockIdx.x >> 6;             // 0..16
    int y0 = (blockIdx.x & 63) << 3;
    int zm = (32 - p) & 31;
#pragma unroll
    for (int k = 0; k < 16; k++) {
        int e = t + k*512;
        int x = e >> 4, L = e & 15;
        int l = L & 7;
        int plane = (L < 8) ? p : zm;
        int y = (L < 8) ? (y0 + l) : ((512 - (y0 + l)) & 511);
        pool16[L*POOLSZ + x] = g_buf[(size_t)plane*PLANE + (size_t)x*512 + y];
    }
    __syncthreads();
    int l0 = t >> 6, u = t & 63;
#pragma unroll
    for (int c = 0; c < 2; c++) {
        int Q = c*8 + l0;
        float2* pool = pool16 + Q*POOLSZ;
        float2 r[8];
#pragma unroll
        for (int b = 0; b < 8; b++) r[b] = pool[u + 64*b];
        fft512_core<false, true>(r, pool, u);
    }
    float2* pool = pool16 + l0*POOLSZ;
    float2* mpool = pool16 + (l0 + 8)*POOLSZ;
    float2 r[8];
#pragma unroll
    for (int b = 0; b < 8; b++) {
        int x = u + 64*b;
        int xm = (512 - x) & 511;
        float2 a  = pool[x + (x>>3)];
        float2 bb = mpool[xm + (xm>>3)];
        float sx = a.x + bb.x, sy = a.y - bb.y;
        float tx = a.x - bb.x, ty = -a.y - bb.y;
        float ur = sx*tx - sy*ty;
        float ui = sx*ty + sy*tx;
        r[b] = make_float2(-0.25f*ui, 0.25f*ur);
    }
    if (p == 0 && y0 == 0 && l0 == 0 && u == 0)
        r[0] = make_float2(0.f, 0.f);   // exact DC of zero-mean cross
    __syncthreads();
    fft512_core<true, true>(r, pool, u);
    float2* dst;
    if (p == 0)       dst = g_side;
    else if (p == 16) dst = g_side + PLANE;
    else              dst = g_buf + (size_t)p*PLANE;
#pragma unroll
    for (int k = 0; k < 8; k++) {
        int e = t + k*512;
        int x = e >> 3, yy = e & 7;
        dst[(size_t)x*512 + (y0 + yy)] = pool16[yy*POOLSZ + x + (x>>3)];
    }
}

// ------- fused inverse y + inverse z + roll/abs/store, 2-for-1 in x ---------
// Planes z=0..16 stored (0,16 in g_side; 1..15 in g_buf); 17..31 are conj
// mirrors: s(x,y,z) = conj(s(x,(512-y)&511, 32-z)).
__global__ void __launch_bounds__(1024) k_inv_yz(float* __restrict__ out) {
    extern __shared__ float2 tile[];   // 32 lines (z) x POOLSZ
    int x1 = blockIdx.x, x2 = x1 + 256;
    int t = threadIdx.x;
#pragma unroll
    for (int k = 0; k < 16; k++) {
        int e = t + k*1024;
        int z = e >> 9, y = e & 511;
        float2 a, b;
        if (z <= 16) {
            const float2* src;
            if (z == 0)       src = g_side;
            else if (z == 16) src = g_side + PLANE;
            else              src = g_buf + (size_t)z*PLANE;
            a = src[(size_t)x1*512 + y];
            b = src[(size_t)x2*512 + y];
        } else {
            int zs = 32 - z;
            int ys = (512 - y) & 511;
            const float2* src = g_buf + (size_t)zs*PLANE;
            a = src[(size_t)x1*512 + ys]; a.y = -a.y;
            b = src[(size_t)x2*512 + ys]; b.y = -b.y;
        }
        tile[z*POOLSZ + y] = make_float2(a.x - b.y, a.y + b.x);
    }
    __syncthreads();
    int l0 = t >> 6, u = t & 63;
#pragma unroll
    for (int c = 0; c < 2; c++) {
        int l = c*16 + l0;
        float2* pool = tile + l*POOLSZ;
        float2 r[8];
#pragma unroll
        for (int b = 0; b < 8; b++) r[b] = pool[u + 64*b];
        fft512_core<true, true>(r, pool, u);
    }
    int w = t >> 5, lane = t & 31;
    int ox1 = (x1 + 256) & 511;   // = x2
    int ox2 = (x2 + 256) & 511;   // = x1
    int oz = (lane + 16) & 31;
    const float inv = 1.0f / (float)NTOT;
#pragma unroll
    for (int i = 0; i < 16; i++) {
        int y = w + 32*i;
        float2 v = tile[lane*POOLSZ + y + (y>>3)];
        v = fft32_warp<true>(v, lane);
        int oy = (y + 256) & 511;
        out[3 + (((ox1 << 9) | oy) << 5) + oz] = fabsf(v.x) * inv;
        out[3 + (((ox2 << 9) | oy) << 5) + oz] = fabsf(v.y) * inv;
    }
}

// ---------------- y-window pass: F - head - tail (block per x) ---------------
__global__ void k_yred() {
    __shared__ float2 sh[512*5];
    __shared__ float2 part[32][5];
    int x = blockIdx.x, t = threadIdx.x;   // 256 threads
    for (int i = t; i < 512*5; i += 256) sh[i] = g_P1[(size_t)x*(512*5) + i];
    __syncthreads();
    if (t < 160) {
        int c = t % 5, chunk = t / 5;
        float A = 0.f, B = 0.f;
#pragma unroll
        for (int j = 0; j < 16; j++) {
            float2 v = sh[(chunk*16 + j)*5 + c];
            A += v.x; B += v.y;
        }
        part[chunk][c] = make_float2(A, B);
    }
    __syncthreads();
    if (t < 5) {
        int c = t;
        float FA = 0.f, FB = 0.f;
#pragma unroll
        for (int k = 0; k < 32; k++) { FA += part[k][c].x; FB += part[k][c].y; }
        float headA[21], headB[21], tailA[21], tailB[21];
        headA[0] = 0.f; headB[0] = 0.f;
        for (int b = 1; b <= 20; b++) {
            float2 v = sh[(b-1)*5 + c];
            headA[b] = headA[b-1] + v.x; headB[b] = headB[b-1] + v.y;
        }
        tailA[20] = 0.f; tailB[20] = 0.f;
        for (int b = 19; b >= 0; b--) {
            float2 v = sh[(b + 492)*5 + c];
            tailA[b] = tailA[b+1] + v.x; tailB[b] = tailB[b+1] + v.y;
        }
        for (int b = 0; b < 21; b++)
            g_P2[(x*BD + b)*5 + c] = make_float2(FA - headA[b] - tailA[b],
                                                 FB - headB[b] - tailB[b]);
    }
}

// ---- x-window + denominator (tplvar reduced inline per block) ---------------
__global__ void k_xred() {
    __shared__ double sp[256];
    __shared__ double s_sum1, s_tv;
    int t = threadIdx.x;
    sp[t] = g_part[1024 + t] + g_part[1024 + 256 + t];
    __syncthreads();
    for (int o = 128; o > 0; o >>= 1) { if (t < o) sp[t] += sp[t+o]; __syncthreads(); }
    if (t == 0) s_sum1 = sp[0];
    __syncthreads();
    sp[t] = g_part[2048 + t] + g_part[2048 + 256 + t];
    __syncthreads();
    for (int o = 128; o > 0; o >>= 1) { if (t < o) sp[t] += sp[t+o]; __syncthreads(); }
    if (t == 0) {
        double mt = s_sum1 / (double)NTOT;
        s_tv = sp[0] - (double)NTOT*mt*mt + EPSV;
    }
    __syncthreads();
    double tplvar = s_tv;
    int gw = blockIdx.x*8 + (t >> 5);
    int lane = t & 31;
    if (gw >= NCCN) return;
    int a = gw / (BD*CD), rr = gw % (BD*CD), b = rr / CD, c = rr % CD;
    double A = 0, B = 0;
    for (int j = lane; j < 492; j += 32) {
        float2 v = g_P2[((size_t)(a + j)*BD + b)*CD + c];
        A += (double)v.x; B += (double)v.y;
    }
#pragma unroll
    for (int o = 16; o > 0; o >>= 1) {
        A += __shfl_down_sync(0xffffffffu, A, o);
        B += __shfl_down_sync(0xffffffffu, B, o);
    }
    if (lane == 0) {
        const double wn = (double)WXW * (double)WYW * (double)WZW;
        double m1 = A / wn, m2 = B / wn;
        double var = m2 - m1*m1/(double)NTOT + EPSV;
        if (var < 0) var = 0;
        g_denom[gw] = sqrt(tplvar * var);
    }
}

// ---------------- ncc + argmax + subpixel (single block) ---------------------
__global__ void k_ncc_argmax(float* __restrict__ out) {
    __shared__ float ncc_s[NCCN];
    __shared__ float sv[256];
    __shared__ int   si[256];
    int t = threadIdx.x;
    for (int q = t; q < NCCN; q += 256) {
        int a = q / (BD*CD), rr = q % (BD*CD), b = rr / CD, c = rr % CD;
        int ridx = ((((246 + a) << 9) | (246 + b)) << 5) | (14 + c);
        float val = out[3 + ridx] / (float)g_denom[q];
        if (val != val) val = 0.0f;
        out[3 + NTOT + q] = val;
        ncc_s[q] = val;
    }
    __syncthreads();
    float bv = -1e30f; int bi = 0x7fffffff;
    for (int q = t; q < NCCN; q += 256) {
        float v = ncc_s[q];
        if (v > bv) { bv = v; bi = q; }
    }
    sv[t] = bv; si[t] = bi; __syncthreads();
    for (int o = 128; o > 0; o >>= 1) {
        if (t < o) {
            if (sv[t+o] > sv[t] || (sv[t+o] == sv[t] && si[t+o] < si[t])) {
                sv[t] = sv[t+o]; si[t] = si[t+o];
            }
        }
        __syncthreads();
    }
    if (t == 0) {
        int idx = si[0];
        int sx = idx / (BD*CD), sy = (idx % (BD*CD)) / CD, sz = idx % CD;
        auto L = [&](int dx, int dy, int dz) {
            int xi = sx + dx; if (xi < 0) xi = 0; if (xi > AD-1) xi = AD-1;
            int yi = sy + dy; if (yi < 0) yi = 0; if (yi > BD-1) yi = BD-1;
            int zi = sz + dz; if (zi < 0) zi = 0; if (zi > CD-1) zi = CD-1;
            return logf(ncc_s[(xi*BD + yi)*CD + zi]);
        };
        float six = 6.0f * L(0,0,0);
        float shx = -(float)(sx - 10) - (L(-1,0,0) - L(1,0,0)) / (2.0f*L(-1,0,0) - six + 2.0f*L(1,0,0));
        float shy = -(float)(sy - 10) - (L(0,-1,0) - L(0,1,0)) / (2.0f*L(0,-1,0) - six + 2.0f*L(0,1,0));
        float shz = -(float)(sz - 2)  - (L(0,0,-1) - L(0,0,1)) / (2.0f*L(0,0,-1) - six + 2.0f*L(0,0,1));
        out[0] = shx; out[1] = shy; out[2] = shz;
    }
}

// ---------------- launch ------------------------------------------------------
extern "C" void kernel_launch(void* const* d_in, const int* in_sizes, int n_in,
                              void* d_out, int out_size) {
    const float* fr  = (const float*)d_in[0];   // (1,512,512,32,1)
    const float* tpl = (const float*)d_in[1];   // (512,512,32,1)
    float* out = (float*)d_out;                 // [shx,shy,shz, rolled_cc(8.4M), ncc(2205)]

    cudaFuncSetAttribute(k_fwd_zy, cudaFuncAttributeMaxDynamicSharedMemorySize, (int)SMEMB);
    cudaFuncSetAttribute(k_inv_yz, cudaFuncAttributeMaxDynamicSharedMemorySize, (int)SMEMB);
    cudaFuncSetAttribute(k_xc,     cudaFuncAttributeMaxDynamicSharedMemorySize, (int)SMEMXC);

    k_init  <<<1, 512>>>();

    // forward z+y FFT + tpl sums + z-window sums (stage-1 in registers)
    k_fwd_zy<<<XD, 1024, SMEMB>>>(fr, tpl);

    // unified forward-x + cross + inverse-x (17 planes, 2 blocks/SM)
    k_xc<<<17*64, 512, SMEMXC>>>();

    // fused inverse y + inverse z + roll/abs (2 x-planes per block, conj mirror)
    k_inv_yz<<<256, 1024, SMEMB>>>(out);

    // denominator chain (tplvar folded into k_xred)
    k_yred<<<XD, 256>>>();
    k_xred<<<(NCCN + 7)/8, 256>>>();

    // ncc + subpixel shifts
    k_ncc_argmax<<<1, 256>>>(out);
}